// round 5
// baseline (speedup 1.0000x reference)
#include <cuda_runtime.h>
#include <cuda_fp16.h>
#include <cstdint>

// fp16 mma.sync attention, cp.async double-buffered, register-resident P.
// Pre-pass converts Q/K/V fp32 -> fp16 into __device__ scratch.
// Main kernel: 1 CTA = (b,h) x 128 q rows; 8 warps x 16 rows each.
// Pass A: rowsums of exp (Q frags in regs, K pipelined). Pass B: recompute S,
// write normalized scores, P kept in registers as A-fragments -> PV mma.

namespace {
constexpr int Bc = 8, Hc = 12, Sc = 1024, Dc = 64;
constexpr int QT = 128, KT = 64, NKT = Sc / KT;
constexpr long long SCORE_ELEMS = (long long)Bc * Hc * Sc * Sc;
constexpr float EC = 0.18033688011112042f;  // log2(e) / 8
constexpr int NELEM = Bc * Hc * Sc * Dc;    // 6291456
constexpr int N4 = NELEM / 4;

constexpr int OFF_Q = 0;                     // 128x64 half = 16KB
constexpr int OFF_K0 = 16384, OFF_K1 = 24576;
constexpr int OFF_V0 = 32768, OFF_V1 = 40960;
constexpr int SMEM_TOTAL = 49152;

__device__ __forceinline__ uint32_t swz(uint32_t off) { return off ^ ((off >> 3) & 0x70); }
__device__ __forceinline__ uint32_t smem_u32(const void* p) {
    uint32_t a;
    asm("{ .reg .u64 t; cvta.to.shared.u64 t, %1; cvt.u32.u64 %0, t; }" : "=r"(a) : "l"(p));
    return a;
}
__device__ __forceinline__ uint32_t h2u(__half2 h) { return *reinterpret_cast<uint32_t*>(&h); }
__device__ __forceinline__ float ex2(float x) {
    float r;
    asm("ex2.approx.f32 %0, %1;" : "=f"(r) : "f"(x));
    return r;
}
__device__ __forceinline__ void ldsm4(uint32_t r[4], uint32_t a) {
    asm volatile("ldmatrix.sync.aligned.m8n8.x4.shared.b16 {%0,%1,%2,%3}, [%4];"
                 : "=r"(r[0]), "=r"(r[1]), "=r"(r[2]), "=r"(r[3]) : "r"(a));
}
__device__ __forceinline__ void ldsm4t(uint32_t r[4], uint32_t a) {
    asm volatile("ldmatrix.sync.aligned.m8n8.x4.trans.shared.b16 {%0,%1,%2,%3}, [%4];"
                 : "=r"(r[0]), "=r"(r[1]), "=r"(r[2]), "=r"(r[3]) : "r"(a));
}
__device__ __forceinline__ void mma16816(float c[4], const uint32_t a[4],
                                         uint32_t b0, uint32_t b1) {
    asm volatile(
        "mma.sync.aligned.m16n8k16.row.col.f32.f16.f16.f32 "
        "{%0,%1,%2,%3}, {%4,%5,%6,%7}, {%8,%9}, {%0,%1,%2,%3};"
        : "+f"(c[0]), "+f"(c[1]), "+f"(c[2]), "+f"(c[3])
        : "r"(a[0]), "r"(a[1]), "r"(a[2]), "r"(a[3]), "r"(b0), "r"(b1));
}
__device__ __forceinline__ void cpa16(uint32_t d, const void* s) {
    asm volatile("cp.async.cg.shared.global [%0], [%1], 16;" :: "r"(d), "l"(s) : "memory");
}
#define CP_COMMIT() asm volatile("cp.async.commit_group;" ::: "memory")
#define CP_WAIT0()  asm volatile("cp.async.wait_group 0;" ::: "memory")
}  // namespace

__device__ __align__(16) __half g_qh[NELEM];
__device__ __align__(16) __half g_kh[NELEM];
__device__ __align__(16) __half g_vh[NELEM];

__global__ __launch_bounds__(256)
void cvt_kernel(const float4* __restrict__ q, const float4* __restrict__ k,
                const float4* __restrict__ v) {
    int i = blockIdx.x * blockDim.x + threadIdx.x;
    const float4* src;
    uint2* dst;
    int j;
    if (i < N4)          { src = q; dst = reinterpret_cast<uint2*>(g_qh); j = i; }
    else if (i < 2 * N4) { src = k; dst = reinterpret_cast<uint2*>(g_kh); j = i - N4; }
    else                 { src = v; dst = reinterpret_cast<uint2*>(g_vh); j = i - 2 * N4; }
    float4 x = src[j];
    dst[j] = make_uint2(h2u(__floats2half2_rn(x.x, x.y)), h2u(__floats2half2_rn(x.z, x.w)));
}

namespace {
// copy one 64x64 fp16 tile (8KB) into swizzled smem via cp.async (2 chunks/thread)
__device__ __forceinline__ void load_tile64(uint32_t dstBase, const __half* gsrc, int tid) {
    #pragma unroll
    for (int i = 0; i < 2; i++) {
        int c = tid + i * 256;
        int r = c >> 3, ch = c & 7;
        cpa16(dstBase + swz((uint32_t)(r * 128 + ch * 16)), gsrc + r * 64 + ch * 8);
    }
}
}  // namespace

__global__ __launch_bounds__(256, 2)
void sdpa_kernel(float* __restrict__ out) {
    extern __shared__ char smem[];
    const uint32_t sb = smem_u32(smem);
    const int tid = threadIdx.x, lane = tid & 31, wid = tid >> 5;
    const int g = lane >> 2, m = lane & 3;
    const int rs = wid * 16;                       // warp owns rows rs..rs+15
    const uint32_t xr = (uint32_t)((lane & 7) << 4);

    const int bh = blockIdx.y, qb = blockIdx.x;
    const __half* qg  = g_qh + ((long long)bh * Sc + qb * QT) * Dc;
    const __half* kgb = g_kh + (long long)bh * Sc * Dc;
    const __half* vgb = g_vh + (long long)bh * Sc * Dc;
    float* score = out + (long long)bh * Sc * Sc + (long long)(qb * QT) * Sc;
    float* ctx   = out + SCORE_ELEMS + ((long long)bh * Sc + qb * QT) * Dc;

    // ---- prologue: Q (16KB) + K tile 0 ----
    #pragma unroll
    for (int i = 0; i < 4; i++) {
        int c = tid + i * 256;
        int r = c >> 3, ch = c & 7;
        cpa16(sb + OFF_Q + swz((uint32_t)(r * 128 + ch * 16)), qg + r * 64 + ch * 8);
    }
    load_tile64(sb + OFF_K0, kgb, tid);
    CP_COMMIT();
    CP_WAIT0();
    __syncthreads();

    // Q fragments in registers, reused for all 32 QK tiles
    uint32_t qf[4][4];
    {
        uint32_t aq = sb + OFF_Q + (uint32_t)((rs + (lane & 15)) * 128);
        #pragma unroll
        for (int kk = 0; kk < 4; kk++)
            ldsm4(qf[kk], aq + (((uint32_t)(kk * 32 + ((lane >> 4) * 16))) ^ xr));
    }

    const uint32_t krow = (uint32_t)((((lane >> 4) << 3) + (lane & 7)) * 128);
    const uint32_t vrow = (uint32_t)((lane & 15) * 128);
    const uint32_t vc0 = (uint32_t)((lane >> 4) * 16);

    // =================== pass A: row sums ===================
    float rsum0 = 0.f, rsum1 = 0.f;
    for (int kt = 0; kt < NKT; kt++) {
        if (kt + 1 < NKT) {
            load_tile64(sb + (((kt + 1) & 1) ? OFF_K1 : OFF_K0),
                        kgb + (long long)(kt + 1) * KT * Dc, tid);
            CP_COMMIT();
        }
        const uint32_t kbase = sb + ((kt & 1) ? OFF_K1 : OFF_K0) + krow;
        float acc[8][4];
        #pragma unroll
        for (int nf = 0; nf < 8; nf++) acc[nf][0] = acc[nf][1] = acc[nf][2] = acc[nf][3] = 0.f;
        #pragma unroll
        for (int kk = 0; kk < 4; kk++) {
            uint32_t kb = ((uint32_t)(kk * 32 + (((lane >> 3) & 1) * 16))) ^ xr;
            #pragma unroll
            for (int nb = 0; nb < 4; nb++) {
                uint32_t B[4];
                ldsm4(B, kbase + (uint32_t)(nb * 2048) + kb);
                mma16816(acc[2 * nb],     qf[kk], B[0], B[1]);
                mma16816(acc[2 * nb + 1], qf[kk], B[2], B[3]);
            }
        }
        #pragma unroll
        for (int nf = 0; nf < 8; nf++) {
            rsum0 += ex2(acc[nf][0] * EC) + ex2(acc[nf][1] * EC);
            rsum1 += ex2(acc[nf][2] * EC) + ex2(acc[nf][3] * EC);
        }
        if (kt + 1 < NKT) { CP_WAIT0(); __syncthreads(); }
    }

    // ---- transition: issue pass-B tile 0 (K0+V0), reduce rowsums meanwhile ----
    load_tile64(sb + OFF_K0, kgb, tid);
    load_tile64(sb + OFF_V0, vgb, tid);
    CP_COMMIT();

    rsum0 += __shfl_xor_sync(0xffffffffu, rsum0, 1);
    rsum0 += __shfl_xor_sync(0xffffffffu, rsum0, 2);
    rsum1 += __shfl_xor_sync(0xffffffffu, rsum1, 1);
    rsum1 += __shfl_xor_sync(0xffffffffu, rsum1, 2);
    const float inv0 = 1.f / rsum0, inv1 = 1.f / rsum1;

    CP_WAIT0();
    __syncthreads();

    // =================== pass B: scores + context ===================
    float cc[8][4];
    #pragma unroll
    for (int nf = 0; nf < 8; nf++) cc[nf][0] = cc[nf][1] = cc[nf][2] = cc[nf][3] = 0.f;

    for (int kt = 0; kt < NKT; kt++) {
        if (kt + 1 < NKT) {
            uint32_t b = ((kt + 1) & 1) ? 1u : 0u;
            load_tile64(sb + (b ? OFF_K1 : OFF_K0), kgb + (long long)(kt + 1) * KT * Dc, tid);
            load_tile64(sb + (b ? OFF_V1 : OFF_V0), vgb + (long long)(kt + 1) * KT * Dc, tid);
            CP_COMMIT();
        }
        const uint32_t kbase = sb + ((kt & 1) ? OFF_K1 : OFF_K0) + krow;
        const uint32_t vbase = sb + ((kt & 1) ? OFF_V1 : OFF_V0) + vrow;

        float acc[8][4];
        #pragma unroll
        for (int nf = 0; nf < 8; nf++) acc[nf][0] = acc[nf][1] = acc[nf][2] = acc[nf][3] = 0.f;
        #pragma unroll
        for (int kk = 0; kk < 4; kk++) {
            uint32_t kb = ((uint32_t)(kk * 32 + (((lane >> 3) & 1) * 16))) ^ xr;
            #pragma unroll
            for (int nb = 0; nb < 4; nb++) {
                uint32_t B[4];
                ldsm4(B, kbase + (uint32_t)(nb * 2048) + kb);
                mma16816(acc[2 * nb],     qf[kk], B[0], B[1]);
                mma16816(acc[2 * nb + 1], qf[kk], B[2], B[3]);
            }
        }

        // p = exp2(s*EC)*inv, in place; write normalized scores (streaming)
        #pragma unroll
        for (int nf = 0; nf < 8; nf++) {
            acc[nf][0] = ex2(acc[nf][0] * EC) * inv0;
            acc[nf][1] = ex2(acc[nf][1] * EC) * inv0;
            acc[nf][2] = ex2(acc[nf][2] * EC) * inv1;
            acc[nf][3] = ex2(acc[nf][3] * EC) * inv1;
            int colG = kt * KT + nf * 8 + 2 * m;
            __stcs(reinterpret_cast<float2*>(score + (long long)(rs + g) * Sc + colG),
                   make_float2(acc[nf][0], acc[nf][1]));
            __stcs(reinterpret_cast<float2*>(score + (long long)(rs + 8 + g) * Sc + colG),
                   make_float2(acc[nf][2], acc[nf][3]));
        }

        // PV: P stays in registers (C-fragment == A-fragment layout)
        #pragma unroll
        for (int c = 0; c < 4; c++) {   // k chunks of 16 (seq)
            uint32_t pa[4];
            pa[0] = h2u(__floats2half2_rn(acc[2 * c][0],     acc[2 * c][1]));
            pa[1] = h2u(__floats2half2_rn(acc[2 * c][2],     acc[2 * c][3]));
            pa[2] = h2u(__floats2half2_rn(acc[2 * c + 1][0], acc[2 * c + 1][1]));
            pa[3] = h2u(__floats2half2_rn(acc[2 * c + 1][2], acc[2 * c + 1][3]));
            uint32_t vb = vbase + (uint32_t)(c * 2048);
            #pragma unroll
            for (int db = 0; db < 4; db++) {
                uint32_t B[4];
                ldsm4t(B, vb + ((vc0 + (uint32_t)(db * 32)) ^ xr));
                mma16816(cc[2 * db],     pa, B[0], B[1]);
                mma16816(cc[2 * db + 1], pa, B[2], B[3]);
            }
        }
        if (kt + 1 < NKT) { CP_WAIT0(); __syncthreads(); }
    }

    // ---- write context ----
    #pragma unroll
    for (int nf = 0; nf < 8; nf++) {
        int colG = nf * 8 + 2 * m;
        __stcs(reinterpret_cast<float2*>(ctx + (long long)(rs + g) * Dc + colG),
               make_float2(cc[nf][0], cc[nf][1]));
        __stcs(reinterpret_cast<float2*>(ctx + (long long)(rs + 8 + g) * Dc + colG),
               make_float2(cc[nf][2], cc[nf][3]));
    }
}

extern "C" void kernel_launch(void* const* d_in, const int* in_sizes, int n_in,
                              void* d_out, int out_size) {
    (void)in_sizes; (void)n_in; (void)out_size;
    const float4* q = (const float4*)d_in[0];
    const float4* k = (const float4*)d_in[1];
    const float4* v = (const float4*)d_in[2];
    float* out = (float*)d_out;

    cvt_kernel<<<(3 * N4 + 255) / 256, 256>>>(q, k, v);

    cudaFuncSetAttribute(sdpa_kernel,
                         cudaFuncAttributeMaxDynamicSharedMemorySize, SMEM_TOTAL);
    dim3 grid(Sc / QT, Bc * Hc);  // 8 x 96
    sdpa_kernel<<<grid, 256, SMEM_TOTAL>>>(out);
}